// round 3
// baseline (speedup 1.0000x reference)
#include <cuda_runtime.h>

// Problem constants
#define NK 16384                 // finest block size N[2]
#define TK 32                    // k's per block
#define A_ELEMS (21*21*NK)       // 7225344 per (re/im) plane
#define LOGDET_OFF (2*A_ELEMS)   // 14450688
#define ZOUT_OFF (LOGDET_OFF+1)
#define ZTOT (21*NK)             // 344064

struct cf { float x, y; };
__device__ __forceinline__ cf cmul (cf a, cf b){ return {a.x*b.x - a.y*b.y, a.x*b.y + a.y*b.x}; }
__device__ __forceinline__ cf cmulc(cf a, cf b){ return {a.x*b.x + a.y*b.y, a.y*b.x - a.x*b.y}; } // a*conj(b)
__device__ __forceinline__ cf cinv (cf a){ float d = 1.0f/(a.x*a.x + a.y*a.y); return {a.x*d, -a.y*d}; }

__global__ void _fmgp_zero_logdet(float* out){ out[LOGDET_OFF] = 0.0f; }

__global__ __launch_bounds__(672, 2)
void _fmgp_main(const float* __restrict__ l00r, const float* __restrict__ l00i,
                const float* __restrict__ l01r, const float* __restrict__ l01i,
                const float* __restrict__ l02r, const float* __restrict__ l02i,
                const float* __restrict__ l11r, const float* __restrict__ l11i,
                const float* __restrict__ l12r, const float* __restrict__ l12i,
                const float* __restrict__ l22r, const float* __restrict__ l22i,
                const float* __restrict__ zr,   const float* __restrict__ zi,
                float* __restrict__ out)
{
    __shared__ float2 shA1[4][5][5][TK];   // A1_j blocks, 25.6 KB
    __shared__ float2 shT2[20][TK];        // 5.1 KB
    __shared__ float2 shZ[21][TK];         // 5.4 KB
    __shared__ float2 shM[20][TK];         // 5.1 KB (M2 reduction scratch)
    __shared__ float2 shIS2[TK];           // 1/S2
    __shared__ float  shLD;

    const int kk = threadIdx.x;
    const int k  = blockIdx.x * TK + kk;
    const int y  = threadIdx.y;

    if (y == 0 && kk == 0) shLD = 0.0f;
    __syncthreads();

    // stage z[q,k]
    if (y < 21) shZ[y][kk] = make_float2(zr[y*NK + k], zi[y*NK + k]);

    // ---- Phase A: step-1 per (k, j) with j = y < 4 ----
    if (y < 4) {
        const int i = y*NK + k;                 // index into level-1 arrays
        cf A0[4], T1[4];
        cf M1 = {0.f, 0.f};
        float ld = 0.f;
        #pragma unroll
        for (int j0 = 0; j0 < 4; j0++) {
            const int i0 = j0*65536 + i;        // index into level-0 arrays
            cf L00 = { l00r[i0], l00i[i0] };
            cf B1  = { l01r[i0], l01i[i0] };
            A0[j0] = cinv(L00);
            T1[j0] = cmul(B1, A0[j0]);
            // M1 += conj(B1) * T1
            M1.x += B1.x*T1[j0].x + B1.y*T1[j0].y;
            M1.y += B1.x*T1[j0].y - B1.y*T1[j0].x;
            ld += 0.5f * logf(L00.x*L00.x + L00.y*L00.y);
        }
        cf S1 = { l11r[i] - M1.x, l11i[i] - M1.y };
        ld += 0.5f * logf(S1.x*S1.x + S1.y*S1.y);
        cf iS1 = cinv(S1);
        cf P1[4];
        #pragma unroll
        for (int a = 0; a < 4; a++) P1[a] = cmul(T1[a], iS1);
        // A1_j[a,b] = P1[a]*conj(T1[b]) + delta_ab*A0[a]; borders -P1 / -conj(P1) / 1/S1
        #pragma unroll
        for (int a = 0; a < 4; a++) {
            #pragma unroll
            for (int b = 0; b < 4; b++) {
                cf v = cmulc(P1[a], T1[b]);
                if (a == b) { v.x += A0[a].x; v.y += A0[a].y; }
                shA1[y][a][b][kk] = make_float2(v.x, v.y);
            }
            shA1[y][a][4][kk] = make_float2(-P1[a].x, -P1[a].y);
            shA1[y][4][a][kk] = make_float2(-P1[a].x,  P1[a].y);   // -conj(P1)
        }
        shA1[y][4][4][kk] = make_float2(iS1.x, iS1.y);
        atomicAdd(&shLD, ld);
    }
    __syncthreads();

    // ---- Phase B: T2 rows (p = y < 20), p = a*4 + j ----
    if (y < 20) {
        const int a = y >> 2, j = y & 3;
        cf t = {0.f, 0.f};
        #pragma unroll
        for (int b = 0; b < 5; b++) {
            const int row = b*4 + j;            // B2 row index
            cf Bv;
            if (row < 16) Bv = { l02r[row*NK + k],      l02i[row*NK + k]      };
            else          Bv = { l12r[(row-16)*NK + k], l12i[(row-16)*NK + k] };
            float2 A = shA1[j][a][b][kk];
            t.x += Bv.x*A.x - Bv.y*A.y;
            t.y += Bv.x*A.y + Bv.y*A.x;
        }
        shT2[y][kk] = make_float2(t.x, t.y);
        cf By;
        if (y < 16) By = { l02r[y*NK + k],      l02i[y*NK + k]      };
        else        By = { l12r[(y-16)*NK + k], l12i[(y-16)*NK + k] };
        // conj(B2)*T2
        shM[y][kk] = make_float2(By.x*t.x + By.y*t.y, By.x*t.y - By.y*t.x);
    }
    __syncthreads();

    if (y == 0) {
        float mx = 0.f, my = 0.f;
        #pragma unroll
        for (int p = 0; p < 20; p++) { mx += shM[p][kk].x; my += shM[p][kk].y; }
        cf S2 = { l22r[k] - mx, l22i[k] - my };
        cf iS2 = cinv(S2);
        shIS2[kk] = make_float2(iS2.x, iS2.y);
        atomicAdd(&shLD, 0.5f * logf(S2.x*S2.x + S2.y*S2.y));
    }
    __syncthreads();

    if (y == 0 && kk == 0) atomicAdd(&out[LOGDET_OFF], shLD);

    // ---- Phase C: emit row y of the 21x21 block + zout ----
    {
        cf iS2 = { shIS2[kk].x, shIS2[kk].y };
        cf u = {0.f, 0.f};
        if (y < 20) { float2 t = shT2[y][kk]; u = cmul({t.x, t.y}, iS2); }  // P2[p]
        const int pj = y & 3, pa = y >> 2;
        cf zacc = {0.f, 0.f};
        float* outre = out + (y*21)*NK + k;
        float* outim = outre + A_ELEMS;
        #pragma unroll
        for (int q = 0; q < 21; q++) {
            cf val;
            if (y < 20) {
                if (q < 20) {
                    float2 t = shT2[q][kk];
                    val = cmulc(u, {t.x, t.y});                  // P2[p]*conj(T2[q])
                    if ((q & 3) == pj) {
                        float2 A = shA1[pj][pa][q >> 2][kk];     // + A1_j scatter
                        val.x += A.x; val.y += A.y;
                    }
                } else {
                    val = { -u.x, -u.y };                        // -P2[p]
                }
            } else {
                if (q < 20) {
                    float2 t = shT2[q][kk];
                    cf p2 = cmul({t.x, t.y}, iS2);
                    val = { -p2.x, p2.y };                       // -conj(P2[q])
                } else {
                    val = iS2;                                   // 1/S2
                }
            }
            outre[q*NK] = val.x;
            outim[q*NK] = val.y;
            float2 zq = shZ[q][kk];
            zacc.x += val.x*zq.x - val.y*zq.y;
            zacc.y += val.x*zq.y + val.y*zq.x;
        }
        out[ZOUT_OFF + y*NK + k]        = zacc.x;
        out[ZOUT_OFF + ZTOT + y*NK + k] = zacc.y;
    }
}

extern "C" void kernel_launch(void* const* d_in, const int* in_sizes, int n_in,
                              void* d_out, int out_size)
{
    const float* l00r = (const float*)d_in[0];
    const float* l00i = (const float*)d_in[1];
    const float* l01r = (const float*)d_in[2];
    const float* l01i = (const float*)d_in[3];
    const float* l02r = (const float*)d_in[4];
    const float* l02i = (const float*)d_in[5];
    const float* l11r = (const float*)d_in[6];
    const float* l11i = (const float*)d_in[7];
    const float* l12r = (const float*)d_in[8];
    const float* l12i = (const float*)d_in[9];
    const float* l22r = (const float*)d_in[10];
    const float* l22i = (const float*)d_in[11];
    const float* zr   = (const float*)d_in[12];
    const float* zi   = (const float*)d_in[13];
    float* out = (float*)d_out;

    _fmgp_zero_logdet<<<1, 1>>>(out);
    dim3 block(TK, 21);
    dim3 grid(NK / TK);
    _fmgp_main<<<grid, block>>>(l00r, l00i, l01r, l01i, l02r, l02i,
                                l11r, l11i, l12r, l12i, l22r, l22i,
                                zr, zi, out);
}

// round 4
// speedup vs baseline: 1.3249x; 1.3249x over previous
#include <cuda_runtime.h>

// Problem constants
#define NK 16384                 // finest block size N[2]
#define KB 32                    // k's per block
#define A_ELEMS (21*21*NK)       // 7225344 per (re/im) plane
#define LOGDET_OFF (2*A_ELEMS)   // 14450688
#define ZOUT_OFF (LOGDET_OFF+1)
#define ZTOT (21*NK)             // 344064

__global__ void _fmgp_zero_logdet(float* out){ out[LOGDET_OFF] = 0.0f; }

__global__ __launch_bounds__(168, 4)
void _fmgp_main(const float* __restrict__ l00r, const float* __restrict__ l00i,
                const float* __restrict__ l01r, const float* __restrict__ l01i,
                const float* __restrict__ l02r, const float* __restrict__ l02i,
                const float* __restrict__ l11r, const float* __restrict__ l11i,
                const float* __restrict__ l12r, const float* __restrict__ l12i,
                const float* __restrict__ l22r, const float* __restrict__ l22i,
                const float* __restrict__ zr,   const float* __restrict__ zi,
                float* __restrict__ out)
{
    __shared__ float A1r[4][5][5][KB], A1i[4][5][5][KB];   // 25.6 KB
    __shared__ float T2r[20][KB],      T2i[20][KB];        // 5.12 KB
    __shared__ float Zr [21][KB],      Zi [21][KB];        // 5.38 KB
    __shared__ float Mr [20][KB],      Mi [20][KB];        // 5.12 KB
    __shared__ float ISr[KB],          ISi[KB];            // 256 B
    __shared__ float sLD;

    const int tid   = threadIdx.x;
    const int kbase = blockIdx.x * KB;
    const int yy    = tid >> 3;        // row 0..20
    const int qd    = tid & 7;         // quad 0..7
    const int q4    = qd * 4;          // k offset within block

    if (tid == 0) sLD = 0.0f;

    // ---- stage z (all 168 threads, float4) ----
    *(float4*)&Zr[yy][q4] = *(const float4*)(zr + yy*NK + kbase + q4);
    *(float4*)&Zi[yy][q4] = *(const float4*)(zi + yy*NK + kbase + q4);
    __syncthreads();

    // ---- Phase A: step-1 per (k, j). tid<128: k = tid&31, j = tid>>5 ----
    if (tid < 128) {
        const int kl = tid & 31;
        const int j  = tid >> 5;
        const int i1 = j*NK + kbase + kl;
        float A0r_[4], A0i_[4], T1r_[4], T1i_[4];
        float m1r = 0.f, m1i = 0.f, ld = 0.f;
        #pragma unroll
        for (int j0 = 0; j0 < 4; j0++) {
            const int i0 = j0*65536 + i1;
            float ar = l00r[i0], ai = l00i[i0];
            float br = l01r[i0], bi = l01i[i0];
            float n  = ar*ar + ai*ai;
            float d  = 1.0f/n;
            float inr = ar*d, ini = -ai*d;
            A0r_[j0] = inr; A0i_[j0] = ini;
            float tr = br*inr - bi*ini, ti = br*ini + bi*inr;
            T1r_[j0] = tr; T1i_[j0] = ti;
            m1r += br*tr + bi*ti;
            m1i += br*ti - bi*tr;
            ld  += 0.5f*logf(n);
        }
        float s1r = l11r[i1] - m1r, s1i = l11i[i1] - m1i;
        float n1 = s1r*s1r + s1i*s1i;
        ld += 0.5f*logf(n1);
        float d1 = 1.0f/n1;
        float isr = s1r*d1, isi = -s1i*d1;
        float P1r_[4], P1i_[4];
        #pragma unroll
        for (int a = 0; a < 4; a++) {
            P1r_[a] = T1r_[a]*isr - T1i_[a]*isi;
            P1i_[a] = T1r_[a]*isi + T1i_[a]*isr;
        }
        #pragma unroll
        for (int a = 0; a < 4; a++) {
            #pragma unroll
            for (int b = 0; b < 4; b++) {
                float vr = P1r_[a]*T1r_[b] + P1i_[a]*T1i_[b];   // P1[a]*conj(T1[b])
                float vi = P1i_[a]*T1r_[b] - P1r_[a]*T1i_[b];
                if (a == b) { vr += A0r_[a]; vi += A0i_[a]; }
                A1r[j][a][b][kl] = vr; A1i[j][a][b][kl] = vi;
            }
            A1r[j][a][4][kl] = -P1r_[a]; A1i[j][a][4][kl] = -P1i_[a];
            A1r[j][4][a][kl] = -P1r_[a]; A1i[j][4][a][kl] =  P1i_[a];  // -conj(P1)
        }
        A1r[j][4][4][kl] = isr; A1i[j][4][4][kl] = isi;
        atomicAdd(&sLD, ld);
    }
    __syncthreads();

    // ---- Phase B: T2 rows. tid<160: row = tid>>3 (p = a*4+j), quad qd ----
    if (tid < 160) {
        const int row = tid >> 3;
        const int a = row >> 2, j = row & 3;
        float tr[4] = {0,0,0,0}, ti[4] = {0,0,0,0};
        float Byr[4], Byi[4];
        #pragma unroll
        for (int b = 0; b < 5; b++) {
            const int r2 = b*4 + j;
            const float* pr = (r2 < 16) ? (l02r + r2*NK) : (l12r + (r2-16)*NK);
            const float* pi = (r2 < 16) ? (l02i + r2*NK) : (l12i + (r2-16)*NK);
            float4 br4 = *(const float4*)(pr + kbase + q4);
            float4 bi4 = *(const float4*)(pi + kbase + q4);
            float4 Ar4 = *(const float4*)&A1r[j][a][b][q4];
            float4 Ai4 = *(const float4*)&A1i[j][a][b][q4];
            const float* brp = (const float*)&br4;
            const float* bip = (const float*)&bi4;
            const float* arp = (const float*)&Ar4;
            const float* aip = (const float*)&Ai4;
            #pragma unroll
            for (int c = 0; c < 4; c++) {
                tr[c] += brp[c]*arp[c] - bip[c]*aip[c];
                ti[c] += brp[c]*aip[c] + bip[c]*arp[c];
            }
            if (b == a) {
                #pragma unroll
                for (int c = 0; c < 4; c++) { Byr[c] = brp[c]; Byi[c] = bip[c]; }
            }
        }
        float4 t4r, t4i, m4r, m4i;
        float* pt4r = (float*)&t4r; float* pt4i = (float*)&t4i;
        float* pm4r = (float*)&m4r; float* pm4i = (float*)&m4i;
        #pragma unroll
        for (int c = 0; c < 4; c++) {
            pt4r[c] = tr[c]; pt4i[c] = ti[c];
            pm4r[c] = Byr[c]*tr[c] + Byi[c]*ti[c];   // conj(By)*t
            pm4i[c] = Byr[c]*ti[c] - Byi[c]*tr[c];
        }
        *(float4*)&T2r[row][q4] = t4r; *(float4*)&T2i[row][q4] = t4i;
        *(float4*)&Mr [row][q4] = m4r; *(float4*)&Mi [row][q4] = m4i;
    }
    __syncthreads();

    // ---- S2: tid<8, each reduces 20 rows for its quad ----
    if (tid < 8) {
        const int qq = tid * 4;
        float mr[4] = {0,0,0,0}, mi[4] = {0,0,0,0};
        #pragma unroll
        for (int p = 0; p < 20; p++) {
            float4 r4 = *(float4*)&Mr[p][qq];
            float4 i4 = *(float4*)&Mi[p][qq];
            mr[0] += r4.x; mr[1] += r4.y; mr[2] += r4.z; mr[3] += r4.w;
            mi[0] += i4.x; mi[1] += i4.y; mi[2] += i4.z; mi[3] += i4.w;
        }
        float ld = 0.f;
        float4 is4r, is4i;
        float* pisr = (float*)&is4r; float* pisi = (float*)&is4i;
        #pragma unroll
        for (int c = 0; c < 4; c++) {
            float sr = l22r[kbase + qq + c] - mr[c];
            float si = l22i[kbase + qq + c] - mi[c];
            float n  = sr*sr + si*si;
            ld += 0.5f*logf(n);
            float d = 1.0f/n;
            pisr[c] = sr*d; pisi[c] = -si*d;
        }
        *(float4*)&ISr[qq] = is4r; *(float4*)&ISi[qq] = is4i;
        atomicAdd(&sLD, ld);
    }
    __syncthreads();

    if (tid == 0) atomicAdd(&out[LOGDET_OFF], sLD);

    // ---- Phase C: emit row yy of the 21x21 block + zout, 4 k per thread ----
    {
        float isr[4], isi[4];
        {
            float4 r4 = *(float4*)&ISr[q4];
            float4 i4 = *(float4*)&ISi[q4];
            isr[0]=r4.x; isr[1]=r4.y; isr[2]=r4.z; isr[3]=r4.w;
            isi[0]=i4.x; isi[1]=i4.y; isi[2]=i4.z; isi[3]=i4.w;
        }
        float ur[4] = {0,0,0,0}, ui[4] = {0,0,0,0};
        if (yy < 20) {
            float4 r4 = *(float4*)&T2r[yy][q4];
            float4 i4 = *(float4*)&T2i[yy][q4];
            const float* tr = (const float*)&r4;
            const float* ti = (const float*)&i4;
            #pragma unroll
            for (int c = 0; c < 4; c++) {
                ur[c] = tr[c]*isr[c] - ti[c]*isi[c];  // P2[yy]
                ui[c] = tr[c]*isi[c] + ti[c]*isr[c];
            }
        }
        const int pj = yy & 3, pa = yy >> 2;
        float zar[4] = {0,0,0,0}, zai[4] = {0,0,0,0};
        float* outre = out + (yy*21)*NK + kbase + q4;
        float* outim = outre + A_ELEMS;
        #pragma unroll
        for (int q = 0; q < 21; q++) {
            float vr[4], vi[4];
            if (yy < 20) {
                if (q < 20) {
                    float4 r4 = *(float4*)&T2r[q][q4];
                    float4 i4 = *(float4*)&T2i[q][q4];
                    const float* tqr = (const float*)&r4;
                    const float* tqi = (const float*)&i4;
                    #pragma unroll
                    for (int c = 0; c < 4; c++) {
                        vr[c] = ur[c]*tqr[c] + ui[c]*tqi[c];    // P2*conj(T2[q])
                        vi[c] = ui[c]*tqr[c] - ur[c]*tqi[c];
                    }
                    if ((q & 3) == pj) {                        // A1_j scatter add
                        float4 ar4 = *(float4*)&A1r[pj][pa][q >> 2][q4];
                        float4 ai4 = *(float4*)&A1i[pj][pa][q >> 2][q4];
                        const float* ap = (const float*)&ar4;
                        const float* bp = (const float*)&ai4;
                        #pragma unroll
                        for (int c = 0; c < 4; c++) { vr[c] += ap[c]; vi[c] += bp[c]; }
                    }
                } else {
                    #pragma unroll
                    for (int c = 0; c < 4; c++) { vr[c] = -ur[c]; vi[c] = -ui[c]; }
                }
            } else {
                if (q < 20) {
                    float4 r4 = *(float4*)&T2r[q][q4];
                    float4 i4 = *(float4*)&T2i[q][q4];
                    const float* tqr = (const float*)&r4;
                    const float* tqi = (const float*)&i4;
                    #pragma unroll
                    for (int c = 0; c < 4; c++) {               // -conj(P2[q])
                        float p2r = tqr[c]*isr[c] - tqi[c]*isi[c];
                        float p2i = tqr[c]*isi[c] + tqi[c]*isr[c];
                        vr[c] = -p2r; vi[c] = p2i;
                    }
                } else {
                    #pragma unroll
                    for (int c = 0; c < 4; c++) { vr[c] = isr[c]; vi[c] = isi[c]; }
                }
            }
            float4 o4r, o4i;
            float* pr = (float*)&o4r; float* pi = (float*)&o4i;
            #pragma unroll
            for (int c = 0; c < 4; c++) { pr[c] = vr[c]; pi[c] = vi[c]; }
            *(float4*)(outre + q*NK) = o4r;
            *(float4*)(outim + q*NK) = o4i;
            float4 zr4 = *(float4*)&Zr[q][q4];
            float4 zi4 = *(float4*)&Zi[q][q4];
            const float* zqr = (const float*)&zr4;
            const float* zqi = (const float*)&zi4;
            #pragma unroll
            for (int c = 0; c < 4; c++) {
                zar[c] += vr[c]*zqr[c] - vi[c]*zqi[c];
                zai[c] += vr[c]*zqi[c] + vi[c]*zqr[c];
            }
        }
        // zout base (ZOUT_OFF) is odd -> not 16B aligned; scalar stores
        #pragma unroll
        for (int c = 0; c < 4; c++) {
            out[ZOUT_OFF +        yy*NK + kbase + q4 + c] = zar[c];
            out[ZOUT_OFF + ZTOT + yy*NK + kbase + q4 + c] = zai[c];
        }
    }
}

extern "C" void kernel_launch(void* const* d_in, const int* in_sizes, int n_in,
                              void* d_out, int out_size)
{
    const float* l00r = (const float*)d_in[0];
    const float* l00i = (const float*)d_in[1];
    const float* l01r = (const float*)d_in[2];
    const float* l01i = (const float*)d_in[3];
    const float* l02r = (const float*)d_in[4];
    const float* l02i = (const float*)d_in[5];
    const float* l11r = (const float*)d_in[6];
    const float* l11i = (const float*)d_in[7];
    const float* l12r = (const float*)d_in[8];
    const float* l12i = (const float*)d_in[9];
    const float* l22r = (const float*)d_in[10];
    const float* l22i = (const float*)d_in[11];
    const float* zr   = (const float*)d_in[12];
    const float* zi   = (const float*)d_in[13];
    float* out = (float*)d_out;

    _fmgp_zero_logdet<<<1, 1>>>(out);
    _fmgp_main<<<NK / KB, 168>>>(l00r, l00i, l01r, l01i, l02r, l02i,
                                 l11r, l11i, l12r, l12i, l22r, l22i,
                                 zr, zi, out);
}

// round 5
// speedup vs baseline: 1.4181x; 1.0704x over previous
#include <cuda_runtime.h>

// Problem constants
#define NK 16384                 // finest block size N[2]
#define KB 32                    // k's per block
#define A_ELEMS (21*21*NK)       // 7225344 per (re/im) plane
#define LOGDET_OFF (2*A_ELEMS)   // 14450688
#define ZOUT_OFF (LOGDET_OFF+1)
#define ZTOT (21*NK)             // 344064

__global__ void _fmgp_zero_logdet(float* out){ out[LOGDET_OFF] = 0.0f; }

__global__ __launch_bounds__(336, 4)
void _fmgp_main(const float* __restrict__ l00r, const float* __restrict__ l00i,
                const float* __restrict__ l01r, const float* __restrict__ l01i,
                const float* __restrict__ l02r, const float* __restrict__ l02i,
                const float* __restrict__ l11r, const float* __restrict__ l11i,
                const float* __restrict__ l12r, const float* __restrict__ l12i,
                const float* __restrict__ l22r, const float* __restrict__ l22i,
                const float* __restrict__ zr,   const float* __restrict__ zi,
                float* __restrict__ out)
{
    __shared__ float A1r[4][5][5][KB], A1i[4][5][5][KB];   // 25.6 KB
    __shared__ float T2r[20][KB],      T2i[20][KB];        // 5.12 KB
    __shared__ float Zr [21][KB],      Zi [21][KB];        // 5.38 KB
    __shared__ float Mr [20][KB],      Mi [20][KB];        // 5.12 KB
    __shared__ float ISr[KB],          ISi[KB];            // 256 B
    __shared__ float sLD;

    const int tid   = threadIdx.x;
    const int kbase = blockIdx.x * KB;
    const int yy    = tid >> 4;        // row 0..20
    const int k2    = (tid & 15) * 2;  // k offset (pair) within block

    if (tid == 0) sLD = 0.0f;

    // ---- stage z (all 336 threads, float2) ----
    *(float2*)&Zr[yy][k2] = *(const float2*)(zr + yy*NK + kbase + k2);
    *(float2*)&Zi[yy][k2] = *(const float2*)(zi + yy*NK + kbase + k2);
    __syncthreads();

    // ---- Phase A: step-1 per (k, j). tid<128: kl = tid&31, j = tid>>5 ----
    if (tid < 128) {
        const int kl = tid & 31;
        const int j  = tid >> 5;
        const int i1 = j*NK + kbase + kl;
        float A0r_[4], A0i_[4], T1r_[4], T1i_[4];
        float m1r = 0.f, m1i = 0.f, ld = 0.f;
        #pragma unroll
        for (int j0 = 0; j0 < 4; j0++) {
            const int i0 = j0*65536 + i1;
            float ar = l00r[i0], ai = l00i[i0];
            float br = l01r[i0], bi = l01i[i0];
            float n  = ar*ar + ai*ai;
            float d  = __fdividef(1.0f, n);
            float inr = ar*d, ini = -ai*d;
            A0r_[j0] = inr; A0i_[j0] = ini;
            float tr = br*inr - bi*ini, ti = br*ini + bi*inr;
            T1r_[j0] = tr; T1i_[j0] = ti;
            m1r += br*tr + bi*ti;
            m1i += br*ti - bi*tr;
            ld  += 0.5f*__logf(n);
        }
        float s1r = l11r[i1] - m1r, s1i = l11i[i1] - m1i;
        float n1 = s1r*s1r + s1i*s1i;
        ld += 0.5f*__logf(n1);
        float d1 = __fdividef(1.0f, n1);
        float isr = s1r*d1, isi = -s1i*d1;
        #pragma unroll
        for (int a = 0; a < 4; a++) {
            float p1r = T1r_[a]*isr - T1i_[a]*isi;   // P1[a]
            float p1i = T1r_[a]*isi + T1i_[a]*isr;
            #pragma unroll
            for (int b = 0; b < 4; b++) {
                float vr = p1r*T1r_[b] + p1i*T1i_[b];   // P1[a]*conj(T1[b])
                float vi = p1i*T1r_[b] - p1r*T1i_[b];
                if (a == b) { vr += A0r_[a]; vi += A0i_[a]; }
                A1r[j][a][b][kl] = vr; A1i[j][a][b][kl] = vi;
            }
            A1r[j][a][4][kl] = -p1r; A1i[j][a][4][kl] = -p1i;
            A1r[j][4][a][kl] = -p1r; A1i[j][4][a][kl] =  p1i;   // -conj(P1)
        }
        A1r[j][4][4][kl] = isr; A1i[j][4][4][kl] = isi;
        atomicAdd(&sLD, ld);
    }
    __syncthreads();

    // ---- Phase B: T2 rows. tid<320: row = tid>>4 (p = a*4+j), pair k2 ----
    if (tid < 320) {
        const int row = yy;                 // 0..19
        const int a = row >> 2, j = row & 3;
        float tr0=0.f, ti0=0.f, tr1=0.f, ti1=0.f;
        float Byr0=0.f, Byi0=0.f, Byr1=0.f, Byi1=0.f;
        #pragma unroll
        for (int b = 0; b < 5; b++) {
            const int r2 = b*4 + j;
            const float* pr = (r2 < 16) ? (l02r + r2*NK) : (l12r + (r2-16)*NK);
            const float* pi = (r2 < 16) ? (l02i + r2*NK) : (l12i + (r2-16)*NK);
            float2 br = *(const float2*)(pr + kbase + k2);
            float2 bi = *(const float2*)(pi + kbase + k2);
            float2 Ar = *(float2*)&A1r[j][a][b][k2];
            float2 Ai = *(float2*)&A1i[j][a][b][k2];
            tr0 += br.x*Ar.x - bi.x*Ai.x;  ti0 += br.x*Ai.x + bi.x*Ar.x;
            tr1 += br.y*Ar.y - bi.y*Ai.y;  ti1 += br.y*Ai.y + bi.y*Ar.y;
            if (b == a) { Byr0 = br.x; Byi0 = bi.x; Byr1 = br.y; Byi1 = bi.y; }
        }
        *(float2*)&T2r[row][k2] = make_float2(tr0, tr1);
        *(float2*)&T2i[row][k2] = make_float2(ti0, ti1);
        // conj(By)*t
        *(float2*)&Mr[row][k2] = make_float2(Byr0*tr0 + Byi0*ti0, Byr1*tr1 + Byi1*ti1);
        *(float2*)&Mi[row][k2] = make_float2(Byr0*ti0 - Byi0*tr0, Byr1*ti1 - Byi1*tr1);
    }
    __syncthreads();

    // ---- S2: 32 threads, one per k (conflict-free scalar LDS) ----
    if (tid < 32) {
        const int kl = tid;
        float mr = 0.f, mi = 0.f;
        #pragma unroll
        for (int p = 0; p < 20; p++) { mr += Mr[p][kl]; mi += Mi[p][kl]; }
        float sr = l22r[kbase + kl] - mr;
        float si = l22i[kbase + kl] - mi;
        float n  = sr*sr + si*si;
        float d  = __fdividef(1.0f, n);
        ISr[kl] = sr*d; ISi[kl] = -si*d;
        atomicAdd(&sLD, 0.5f*__logf(n));
    }
    __syncthreads();

    if (tid == 0) atomicAdd(&out[LOGDET_OFF], sLD);

    // ---- Phase C: emit row yy of the 21x21 block + zout, 2 k per thread ----
    {
        const float2 isr2 = *(float2*)&ISr[k2];
        const float2 isi2 = *(float2*)&ISi[k2];
        float ur0=0.f, ui0=0.f, ur1=0.f, ui1=0.f;
        if (yy < 20) {
            float2 t_r = *(float2*)&T2r[yy][k2];
            float2 t_i = *(float2*)&T2i[yy][k2];
            ur0 = t_r.x*isr2.x - t_i.x*isi2.x;  ui0 = t_r.x*isi2.x + t_i.x*isr2.x;
            ur1 = t_r.y*isr2.y - t_i.y*isi2.y;  ui1 = t_r.y*isi2.y + t_i.y*isr2.y;
        }
        const int pj = yy & 3, pa = yy >> 2;
        float za0r=0.f, za0i=0.f, za1r=0.f, za1i=0.f;
        float* outre = out + (yy*21)*NK + kbase + k2;
        float* outim = outre + A_ELEMS;
        #pragma unroll
        for (int q = 0; q < 21; q++) {
            float v0r, v0i, v1r, v1i;
            if (yy < 20) {
                if (q < 20) {
                    float2 tqr = *(float2*)&T2r[q][k2];
                    float2 tqi = *(float2*)&T2i[q][k2];
                    v0r = ur0*tqr.x + ui0*tqi.x;  v0i = ui0*tqr.x - ur0*tqi.x;
                    v1r = ur1*tqr.y + ui1*tqi.y;  v1i = ui1*tqr.y - ur1*tqi.y;
                    if ((q & 3) == pj) {                     // A1_j scatter add
                        float2 ar = *(float2*)&A1r[pj][pa][q >> 2][k2];
                        float2 ai = *(float2*)&A1i[pj][pa][q >> 2][k2];
                        v0r += ar.x; v0i += ai.x; v1r += ar.y; v1i += ai.y;
                    }
                } else {
                    v0r = -ur0; v0i = -ui0; v1r = -ur1; v1i = -ui1;
                }
            } else {
                if (q < 20) {                                 // -conj(P2[q])
                    float2 tqr = *(float2*)&T2r[q][k2];
                    float2 tqi = *(float2*)&T2i[q][k2];
                    float p0r = tqr.x*isr2.x - tqi.x*isi2.x;
                    float p0i = tqr.x*isi2.x + tqi.x*isr2.x;
                    float p1r = tqr.y*isr2.y - tqi.y*isi2.y;
                    float p1i = tqr.y*isi2.y + tqi.y*isr2.y;
                    v0r = -p0r; v0i = p0i; v1r = -p1r; v1i = p1i;
                } else {
                    v0r = isr2.x; v0i = isi2.x; v1r = isr2.y; v1i = isi2.y;
                }
            }
            *(float2*)(outre + q*NK) = make_float2(v0r, v1r);
            *(float2*)(outim + q*NK) = make_float2(v0i, v1i);
            float2 zqr = *(float2*)&Zr[q][k2];
            float2 zqi = *(float2*)&Zi[q][k2];
            za0r += v0r*zqr.x - v0i*zqi.x;  za0i += v0r*zqi.x + v0i*zqr.x;
            za1r += v1r*zqr.y - v1i*zqi.y;  za1i += v1r*zqi.y + v1i*zqr.y;
        }
        // ZOUT base is odd -> 4B alignment only; scalar stores
        const int zb = yy*NK + kbase + k2;
        out[ZOUT_OFF + zb]            = za0r;
        out[ZOUT_OFF + zb + 1]        = za1r;
        out[ZOUT_OFF + ZTOT + zb]     = za0i;
        out[ZOUT_OFF + ZTOT + zb + 1] = za1i;
    }
}

extern "C" void kernel_launch(void* const* d_in, const int* in_sizes, int n_in,
                              void* d_out, int out_size)
{
    const float* l00r = (const float*)d_in[0];
    const float* l00i = (const float*)d_in[1];
    const float* l01r = (const float*)d_in[2];
    const float* l01i = (const float*)d_in[3];
    const float* l02r = (const float*)d_in[4];
    const float* l02i = (const float*)d_in[5];
    const float* l11r = (const float*)d_in[6];
    const float* l11i = (const float*)d_in[7];
    const float* l12r = (const float*)d_in[8];
    const float* l12i = (const float*)d_in[9];
    const float* l22r = (const float*)d_in[10];
    const float* l22i = (const float*)d_in[11];
    const float* zr   = (const float*)d_in[12];
    const float* zi   = (const float*)d_in[13];
    float* out = (float*)d_out;

    _fmgp_zero_logdet<<<1, 1>>>(out);
    _fmgp_main<<<NK / KB, 336>>>(l00r, l00i, l01r, l01i, l02r, l02i,
                                 l11r, l11i, l12r, l12i, l22r, l22i,
                                 zr, zi, out);
}